// round 10
// baseline (speedup 1.0000x reference)
#include <cuda_runtime.h>
#include <math.h>

#define NN 10000
#define NE 160000
#define HID 128
#define EMB 64
#define ITERS 16

typedef unsigned long long u64;

// ---------------- packed f32x2 helpers (Blackwell FFMA2) --------------------
__device__ __forceinline__ u64 pack2(float x, float y) {
    u64 r; asm("mov.b64 %0, {%1, %2};" : "=l"(r) : "f"(x), "f"(y)); return r;
}
__device__ __forceinline__ u64 packbc(float x) {
    u64 r; asm("mov.b64 %0, {%1, %1};" : "=l"(r) : "f"(x)); return r;
}
__device__ __forceinline__ void fma2(u64 &d, u64 a, u64 b) {
    asm("fma.rn.f32x2 %0, %1, %2, %0;" : "+l"(d) : "l"(a), "l"(b));
}
__device__ __forceinline__ float2 unpack2(u64 v) {
    float2 o; asm("mov.b64 {%0, %1}, %2;" : "=f"(o.x), "=f"(o.y) : "l"(v)); return o;
}
__device__ __forceinline__ void red_add_v4(float* p, float a, float b, float c, float d) {
    asm volatile("red.global.add.v4.f32 [%0], {%1, %2, %3, %4};"
                 :: "l"(p), "f"(a), "f"(b), "f"(c), "f"(d) : "memory");
}

// ---------------- scratch (device globals; no allocation) -------------------
__device__ __align__(16) float g_h[NN * EMB];
__device__ __align__(16) float g_A[NN * HID];
__device__ __align__(16) float g_B[NN * HID];
__device__ __align__(16) float g_agg[NN * EMB];

// ---------------------------------------------------------------------------
// K_init: h = relu(relu(nf @ iw1 + ib1) @ iw2 + ib2). 128 thr, 16 nodes/blk.
// ---------------------------------------------------------------------------
__global__ void k_init(const float* __restrict__ nf,
                       const float* __restrict__ w1, const float* __restrict__ b1,
                       const float* __restrict__ w2, const float* __restrict__ b2) {
    __shared__ float w1s[2 * 128];
    __shared__ float b1s[128];
    __shared__ float hidS[16 * 132];

    int tid = threadIdx.x;
    int n0 = blockIdx.x * 16;

    w1s[tid] = w1[tid];
    w1s[tid + 128] = w1[tid + 128];
    b1s[tid] = b1[tid];
    __syncthreads();

    for (int it = 0; it < 16; it++) {
        int n = n0 + it;
        float f0 = nf[n * 2 + 0];
        float f1 = nf[n * 2 + 1];
        float v = fmaf(f0, w1s[tid], fmaf(f1, w1s[128 + tid], b1s[tid]));
        hidS[it * 132 + tid] = fmaxf(v, 0.f);
    }
    __syncthreads();

    int node = tid >> 3;
    int c0 = (tid & 7) * 8;
    float acc[8];
#pragma unroll
    for (int j = 0; j < 8; j++) acc[j] = b2[c0 + j];
    for (int k = 0; k < 128; k++) {
        float hv = hidS[node * 132 + k];
#pragma unroll
        for (int j = 0; j < 8; j++) acc[j] = fmaf(hv, __ldg(w2 + k * 64 + c0 + j), acc[j]);
    }
    int n = n0 + node;
#pragma unroll
    for (int j = 0; j < 8; j++) g_h[n * 64 + c0 + j] = fmaxf(acc[j], 0.f);
}

// ---------------------------------------------------------------------------
// K_preAB (standalone, iter-0 only): A[n]=[nf,h]@wA(+bias), B[n]=[nf,h]@wB
// ---------------------------------------------------------------------------
template <int OC, bool ZERO_AGG>
__global__ void k_preAB(const float* __restrict__ nf,
                        const float* __restrict__ wA,
                        const float* __restrict__ wB,
                        const float* __restrict__ bias,
                        const float* __restrict__ h,
                        float* __restrict__ outA,
                        float* __restrict__ outB,
                        float* __restrict__ agg) {
    constexpr int OC2 = 2 * OC;
    constexpr int CJ = OC2 / 32;
    __shared__ float xS[32 * 68];

    int tid = threadIdx.x;
    int n0 = blockIdx.x * 32;

    if (ZERO_AGG) {
        for (int idx = tid; idx < 32 * 64; idx += 256) {
            int n = n0 + (idx >> 6);
            if (n < NN) agg[n * 64 + (idx & 63)] = 0.f;
        }
    }
    for (int idx = tid; idx < 32 * 64; idx += 256) {
        int i = idx >> 6, k = idx & 63;
        int n = n0 + i;
        xS[i * 68 + 2 + k] = (n < NN) ? h[n * 64 + k] : 0.f;
    }
    if (tid < 64) {
        int i = tid >> 1, f = tid & 1;
        int n = n0 + i;
        xS[i * 68 + f] = (n < NN) ? nf[n * 2 + f] : 0.f;
    }
    __syncthreads();

    int tn = (tid >> 5) * 4;
    int c0 = (tid & 31) * CJ;
    bool inA = (c0 < OC);
    int cc = inA ? c0 : (c0 - OC);
    const float* W = (inA ? wA : wB) + cc;

    u64 acc[4][CJ / 2];
    {
        u64 binit[CJ / 2];
#pragma unroll
        for (int j = 0; j < CJ / 2; j++) {
            float b0 = (inA && bias) ? __ldg(bias + cc + 2 * j) : 0.f;
            float b1 = (inA && bias) ? __ldg(bias + cc + 2 * j + 1) : 0.f;
            binit[j] = pack2(b0, b1);
        }
#pragma unroll
        for (int i = 0; i < 4; i++)
#pragma unroll
            for (int j = 0; j < CJ / 2; j++) acc[i][j] = binit[j];
    }

#pragma unroll 2
    for (int k = 0; k < 66; k++) {
        const float* wr = W + k * OC;
        ulonglong2 wa = *(const ulonglong2*)wr;
        ulonglong2 wb;
        if (CJ == 8) wb = *(const ulonglong2*)(wr + 4);
#pragma unroll
        for (int i = 0; i < 4; i++) {
            u64 hh = packbc(xS[(tn + i) * 68 + k]);
            fma2(acc[i][0], hh, wa.x);
            fma2(acc[i][1], hh, wa.y);
            if (CJ == 8) {
                fma2(acc[i][2], hh, wb.x);
                fma2(acc[i][3], hh, wb.y);
            }
        }
    }

    float* OUT = (inA ? outA : outB) + cc;
#pragma unroll
    for (int i = 0; i < 4; i++) {
        int n = n0 + tn + i;
        if (n >= NN) continue;
        float vals[CJ];
#pragma unroll
        for (int j = 0; j < CJ / 2; j++) {
            float2 p = unpack2(acc[i][j]);
            vals[2 * j] = p.x; vals[2 * j + 1] = p.y;
        }
        float* o = OUT + n * OC;
#pragma unroll
        for (int j = 0; j < CJ; j += 4)
            *(float4*)(o + j) = make_float4(vals[j], vals[j + 1], vals[j + 2], vals[j + 3]);
    }
}

// ---------------------------------------------------------------------------
// K_edge (hot): hid = relu(A[dst]+B[src]+d*w132) (128); eh = relu(hid@W2+b2)
// agg[dst] += eh via red.global.add.v4. 128 edges/blk, 256 thr, 8 edges/thr.
// ---------------------------------------------------------------------------
__global__ __launch_bounds__(256, 3)
void k_edge(const float* __restrict__ A, const float* __restrict__ B,
            const float* __restrict__ dist,
            const int* __restrict__ src, const int* __restrict__ dst,
            const float* __restrict__ w2, const float* __restrict__ b2,
            const float* __restrict__ w132,
            float* __restrict__ agg) {
    extern __shared__ float sm[];
    float* hidS = sm;              // 128 rows, stride 130
    __shared__ __align__(16) float w132s[128];
    __shared__ int dstS[128];
    __shared__ int srcS[128];
    __shared__ float dS[128];

    int tid = threadIdx.x;
    int e0 = blockIdx.x * 128;

    if (tid < 128) {
        w132s[tid] = w132[tid];
        dstS[tid] = dst[e0 + tid];
        srcS[tid] = src[e0 + tid];
        dS[tid] = dist[e0 + tid];
    }
    __syncthreads();

    const float4* A4 = (const float4*)A;
    const float4* B4 = (const float4*)B;
    const float4* w4 = (const float4*)w132s;

#pragma unroll
    for (int it = 0; it < 16; it++) {
        int idx = it * 256 + tid;
        int e = idx >> 5, q = idx & 31;
        float4 a = A4[dstS[e] * 32 + q];
        float4 b = B4[srcS[e] * 32 + q];
        float4 w = w4[q];
        float d = dS[e];
        float* hp = hidS + e * 130 + q * 4;
        *(float2*)(hp) = make_float2(fmaxf(fmaf(d, w.x, a.x + b.x), 0.f),
                                     fmaxf(fmaf(d, w.y, a.y + b.y), 0.f));
        *(float2*)(hp + 2) = make_float2(fmaxf(fmaf(d, w.z, a.z + b.z), 0.f),
                                         fmaxf(fmaf(d, w.w, a.w + b.w), 0.f));
    }
    __syncthreads();

    int te = (tid >> 4) * 8;
    int c0 = (tid & 15) * 4;
    u64 acc[8][2];
    {
        u64 b01 = pack2(__ldg(b2 + c0), __ldg(b2 + c0 + 1));
        u64 b23 = pack2(__ldg(b2 + c0 + 2), __ldg(b2 + c0 + 3));
#pragma unroll
        for (int i = 0; i < 8; i++) { acc[i][0] = b01; acc[i][1] = b23; }
    }

#pragma unroll 4
    for (int k = 0; k < 128; k++) {
        ulonglong2 w = *(const ulonglong2*)(w2 + k * 64 + c0);
#pragma unroll
        for (int i = 0; i < 8; i++) {
            u64 hh = packbc(hidS[(te + i) * 130 + k]);
            fma2(acc[i][0], hh, w.x);
            fma2(acc[i][1], hh, w.y);
        }
    }

#pragma unroll
    for (int i = 0; i < 8; i++) {
        float2 p0 = unpack2(acc[i][0]);
        float2 p1 = unpack2(acc[i][1]);
        float* ag = agg + dstS[te + i] * 64 + c0;
        red_add_v4(ag, fmaxf(p0.x, 0.f), fmaxf(p0.y, 0.f),
                       fmaxf(p1.x, 0.f), fmaxf(p1.y, 0.f));
    }
}

// ---------------------------------------------------------------------------
// K_nodeAB (fused): h_new = node MLP([h,nf,agg]); then A/B for the NEXT pass
// from [nf, h_new] in-smem; re-zeroes this tile's agg rows for the next iter.
// OC=128/edge weights for iters 0..14; OC=64/cls weights for iter 15.
// 32-node tiles, 256 thr, f32x2 throughout.
// ---------------------------------------------------------------------------
template <int OC, bool ZERO_NEXT>
__global__ __launch_bounds__(256, 3)
void k_nodeAB(const float* __restrict__ nf,
              float* __restrict__ h,
              float* __restrict__ agg,
              const float* __restrict__ w1, const float* __restrict__ b1,
              const float* __restrict__ w2, const float* __restrict__ b2,
              const float* __restrict__ wA, const float* __restrict__ wB,
              const float* __restrict__ biasA,
              float* __restrict__ outA, float* __restrict__ outB) {
    constexpr int OC2 = 2 * OC;
    constexpr int CJ = OC2 / 32;       // 8 (OC=128) or 4 (OC=64)
    __shared__ float xS[32 * 132];     // phase 1 input; reused as 32x68 in phase 3
    __shared__ float hidS[32 * 132];

    int tid = threadIdx.x;
    int n0 = blockIdx.x * 32;

    // ---- stage x = [h, nf, agg] ----
    for (int idx = tid; idx < 32 * 64; idx += 256) {
        int i = idx >> 6, k = idx & 63;
        int n = n0 + i;
        float hv = 0.f, av = 0.f;
        if (n < NN) { hv = h[n * 64 + k]; av = agg[n * 64 + k]; }
        xS[i * 132 + k] = hv;
        xS[i * 132 + 66 + k] = av;
        if (ZERO_NEXT && n < NN) agg[n * 64 + k] = 0.f;   // re-zero for next iter
    }
    if (tid < 64) {
        int i = tid >> 1, f = tid & 1;
        int n = n0 + i;
        xS[i * 132 + 64 + f] = (n < NN) ? nf[n * 2 + f] : 0.f;
    }
    __syncthreads();

    // ---- layer 1: 32x130 @ 130x128 ----
    {
        int tn = (tid >> 5) * 4;
        int c0 = (tid & 31) * 4;
        u64 acc[4][2];
        u64 b01 = pack2(__ldg(b1 + c0), __ldg(b1 + c0 + 1));
        u64 b23 = pack2(__ldg(b1 + c0 + 2), __ldg(b1 + c0 + 3));
#pragma unroll
        for (int i = 0; i < 4; i++) { acc[i][0] = b01; acc[i][1] = b23; }
#pragma unroll 2
        for (int k0 = 0; k0 < 128; k0 += 4) {
            ulonglong2 wv[4];
#pragma unroll
            for (int u = 0; u < 4; u++)
                wv[u] = *(const ulonglong2*)(w1 + (k0 + u) * 128 + c0);
#pragma unroll
            for (int u = 0; u < 4; u++) {
#pragma unroll
                for (int i = 0; i < 4; i++) {
                    u64 hh = packbc(xS[(tn + i) * 132 + k0 + u]);
                    fma2(acc[i][0], hh, wv[u].x);
                    fma2(acc[i][1], hh, wv[u].y);
                }
            }
        }
#pragma unroll
        for (int k = 128; k < 130; k++) {
            ulonglong2 w = *(const ulonglong2*)(w1 + k * 128 + c0);
#pragma unroll
            for (int i = 0; i < 4; i++) {
                u64 hh = packbc(xS[(tn + i) * 132 + k]);
                fma2(acc[i][0], hh, w.x);
                fma2(acc[i][1], hh, w.y);
            }
        }
#pragma unroll
        for (int i = 0; i < 4; i++) {
            float2 p0 = unpack2(acc[i][0]), p1 = unpack2(acc[i][1]);
            *(float4*)(hidS + (tn + i) * 132 + c0) =
                make_float4(fmaxf(p0.x, 0.f), fmaxf(p0.y, 0.f),
                            fmaxf(p1.x, 0.f), fmaxf(p1.y, 0.f));
        }
    }
    __syncthreads();   // hidS ready; xS dead after this point

    // ---- layer 2: 32x128 @ 128x64 → h_new; write to gmem + xS (as 32x68) ----
    {
        int tn = (tid >> 5) * 4;
        int c0 = (tid & 31) * 2;
        u64 acc[4];
        u64 bi = pack2(__ldg(b2 + c0), __ldg(b2 + c0 + 1));
#pragma unroll
        for (int i = 0; i < 4; i++) acc[i] = bi;
#pragma unroll 4
        for (int k0 = 0; k0 < 128; k0 += 4) {
            u64 wv[4];
#pragma unroll
            for (int u = 0; u < 4; u++)
                wv[u] = *(const u64*)(w2 + (k0 + u) * 64 + c0);
#pragma unroll
            for (int u = 0; u < 4; u++) {
#pragma unroll
                for (int i = 0; i < 4; i++) {
                    u64 hh = packbc(hidS[(tn + i) * 132 + k0 + u]);
                    fma2(acc[i], hh, wv[u]);
                }
            }
        }
#pragma unroll
        for (int i = 0; i < 4; i++) {
            int n = n0 + tn + i;
            float2 p = unpack2(acc[i]);
            float v0 = fmaxf(p.x, 0.f), v1 = fmaxf(p.y, 0.f);
            xS[(tn + i) * 68 + 2 + c0] = v0;          // 32x68 tile for phase 3
            xS[(tn + i) * 68 + 2 + c0 + 1] = v1;
            if (n < NN) {
                h[n * 64 + c0 + 0] = v0;
                h[n * 64 + c0 + 1] = v1;
            }
        }
        if (tid < 64) {
            int i = tid >> 1, f = tid & 1;
            int n = n0 + i;
            xS[i * 68 + f] = (n < NN) ? nf[n * 2 + f] : 0.f;
        }
    }
    __syncthreads();

    // ---- phase 3: A/B precompute from [nf, h_new] (66 x OC2) ----
    {
        int tn = (tid >> 5) * 4;
        int c0 = (tid & 31) * CJ;
        bool inA = (c0 < OC);
        int cc = inA ? c0 : (c0 - OC);
        const float* W = (inA ? wA : wB) + cc;

        u64 acc[4][CJ / 2];
        {
            u64 binit[CJ / 2];
#pragma unroll
            for (int j = 0; j < CJ / 2; j++) {
                float b0 = inA ? __ldg(biasA + cc + 2 * j) : 0.f;
                float b1 = inA ? __ldg(biasA + cc + 2 * j + 1) : 0.f;
                binit[j] = pack2(b0, b1);
            }
#pragma unroll
            for (int i = 0; i < 4; i++)
#pragma unroll
                for (int j = 0; j < CJ / 2; j++) acc[i][j] = binit[j];
        }

#pragma unroll 2
        for (int k = 0; k < 66; k++) {
            const float* wr = W + k * OC;
            ulonglong2 wa = *(const ulonglong2*)wr;
            ulonglong2 wb;
            if (CJ == 8) wb = *(const ulonglong2*)(wr + 4);
#pragma unroll
            for (int i = 0; i < 4; i++) {
                u64 hh = packbc(xS[(tn + i) * 68 + k]);
                fma2(acc[i][0], hh, wa.x);
                fma2(acc[i][1], hh, wa.y);
                if (CJ == 8) {
                    fma2(acc[i][2], hh, wb.x);
                    fma2(acc[i][3], hh, wb.y);
                }
            }
        }

        float* OUT = (inA ? outA : outB) + cc;
#pragma unroll
        for (int i = 0; i < 4; i++) {
            int n = n0 + tn + i;
            if (n >= NN) continue;
            float vals[CJ];
#pragma unroll
            for (int j = 0; j < CJ / 2; j++) {
                float2 p = unpack2(acc[i][j]);
                vals[2 * j] = p.x; vals[2 * j + 1] = p.y;
            }
            float* o = OUT + n * OC;
#pragma unroll
            for (int j = 0; j < CJ; j += 4)
                *(float4*)(o + j) = make_float4(vals[j], vals[j + 1], vals[j + 2], vals[j + 3]);
        }
    }
}

// ---------------------------------------------------------------------------
// K_cls: m = relu(Ac[dst]+Bc[src]+d*w132c) (64); out = sigmoid(m.w2 + b2)
// ---------------------------------------------------------------------------
__global__ void k_cls(const float* __restrict__ Ac, const float* __restrict__ Bc,
                      const float* __restrict__ dist,
                      const int* __restrict__ src, const int* __restrict__ dst,
                      const float* __restrict__ w132c,
                      const float* __restrict__ w2, const float* __restrict__ b2,
                      float* __restrict__ out) {
    __shared__ float w2s[64];
    __shared__ float w1s[64];
    int tid = threadIdx.x;
    if (tid < 64) { w2s[tid] = w2[tid]; w1s[tid] = w132c[tid]; }
    __syncthreads();

    int warp = tid >> 5, lane = tid & 31;
    float b2v = b2[0];
    int ebase = blockIdx.x * 64 + warp * 8;
#pragma unroll
    for (int i = 0; i < 8; i++) {
        int e = ebase + i;
        int dn = dst[e], sn = src[e];
        float d = dist[e];
        float m1 = fmaxf(fmaf(d, w1s[lane], Ac[dn * 64 + lane] + Bc[sn * 64 + lane]), 0.f);
        float m2 = fmaxf(fmaf(d, w1s[lane + 32], Ac[dn * 64 + lane + 32] + Bc[sn * 64 + lane + 32]), 0.f);
        float p = fmaf(m1, w2s[lane], m2 * w2s[lane + 32]);
#pragma unroll
        for (int o = 16; o; o >>= 1) p += __shfl_down_sync(0xffffffffu, p, o);
        if (lane == 0) out[e] = 1.f / (1.f + expf(-(p + b2v)));
    }
}

// ---------------------------------------------------------------------------

extern "C" void kernel_launch(void* const* d_in, const int* in_sizes, int n_in,
                              void* d_out, int out_size) {
    const float* nf   = (const float*)d_in[0];
    const float* dist = (const float*)d_in[1];
    const int*   src  = (const int*)d_in[2];
    const int*   dst  = (const int*)d_in[3];
    const float* iw1 = (const float*)d_in[4];
    const float* ib1 = (const float*)d_in[5];
    const float* iw2 = (const float*)d_in[6];
    const float* ib2 = (const float*)d_in[7];
    const float* ew1 = (const float*)d_in[8];
    const float* eb1 = (const float*)d_in[9];
    const float* ew2 = (const float*)d_in[10];
    const float* eb2 = (const float*)d_in[11];
    const float* nw1 = (const float*)d_in[12];
    const float* nb1 = (const float*)d_in[13];
    const float* nw2 = (const float*)d_in[14];
    const float* nb2 = (const float*)d_in[15];
    const float* cw1 = (const float*)d_in[16];
    const float* cb1 = (const float*)d_in[17];
    const float* cw2 = (const float*)d_in[18];
    const float* cb2 = (const float*)d_in[19];
    float* out = (float*)d_out;

    float *pA, *pB, *pH, *pAgg;
    cudaGetSymbolAddress((void**)&pA, g_A);
    cudaGetSymbolAddress((void**)&pB, g_B);
    cudaGetSymbolAddress((void**)&pH, g_h);
    cudaGetSymbolAddress((void**)&pAgg, g_agg);

    const int EDGE_SMEM = 128 * 130 * 4;        // 66560
    cudaFuncSetAttribute(k_edge, cudaFuncAttributeMaxDynamicSharedMemorySize, EDGE_SMEM);

    const int PRE_BLOCKS  = (NN + 31) / 32;    // 313
    const int EDGE_BLOCKS = NE / 128;          // 1250

    k_init<<<NN / 16, 128>>>(nf, iw1, ib1, iw2, ib2);

    // A/B for iteration 0 (and zero agg)
    k_preAB<128, true><<<PRE_BLOCKS, 256>>>(nf, ew1, ew1 + 66 * 128,
                                            eb1, pH, pA, pB, pAgg);

    for (int it = 0; it < ITERS; it++) {
        k_edge<<<EDGE_BLOCKS, 256, EDGE_SMEM>>>(pA, pB, dist, src, dst,
                                                ew2, eb2, ew1 + 132 * 128, pAgg);
        if (it < ITERS - 1) {
            k_nodeAB<128, true><<<PRE_BLOCKS, 256>>>(nf, pH, pAgg,
                                                     nw1, nb1, nw2, nb2,
                                                     ew1, ew1 + 66 * 128, eb1,
                                                     pA, pB);
        } else {
            k_nodeAB<64, false><<<PRE_BLOCKS, 256>>>(nf, pH, pAgg,
                                                     nw1, nb1, nw2, nb2,
                                                     cw1, cw1 + 66 * 64, cb1,
                                                     pA, pB);
        }
    }

    k_cls<<<NE / 64, 256>>>(pA, pB, dist, src, dst,
                            cw1 + 132 * 64, cw2, cb2, out);
}

// round 11
// speedup vs baseline: 1.0465x; 1.0465x over previous
#include <cuda_runtime.h>
#include <math.h>

#define NN 10000
#define NE 160000
#define HID 128
#define EMB 64
#define ITERS 16

typedef unsigned long long u64;

// ---------------- packed f32x2 helpers (Blackwell FFMA2) --------------------
__device__ __forceinline__ u64 pack2(float x, float y) {
    u64 r; asm("mov.b64 %0, {%1, %2};" : "=l"(r) : "f"(x), "f"(y)); return r;
}
__device__ __forceinline__ u64 packbc(float x) {
    u64 r; asm("mov.b64 %0, {%1, %1};" : "=l"(r) : "f"(x)); return r;
}
__device__ __forceinline__ void fma2(u64 &d, u64 a, u64 b) {
    asm("fma.rn.f32x2 %0, %1, %2, %0;" : "+l"(d) : "l"(a), "l"(b));
}
__device__ __forceinline__ float2 unpack2(u64 v) {
    float2 o; asm("mov.b64 {%0, %1}, %2;" : "=f"(o.x), "=f"(o.y) : "l"(v)); return o;
}
__device__ __forceinline__ void red_add_v4(float* p, float a, float b, float c, float d) {
    asm volatile("red.global.add.v4.f32 [%0], {%1, %2, %3, %4};"
                 :: "l"(p), "f"(a), "f"(b), "f"(c), "f"(d) : "memory");
}

// ---------------- scratch (device globals; no allocation) -------------------
__device__ __align__(16) float g_h[NN * EMB];
__device__ __align__(16) float g_A[NN * HID];
__device__ __align__(16) float g_B[NN * HID];
__device__ __align__(16) float g_agg[NN * EMB];

// ---------------------------------------------------------------------------
// K_init: h = relu(relu(nf @ iw1 + ib1) @ iw2 + ib2). 128 thr, 16 nodes/blk.
// ---------------------------------------------------------------------------
__global__ void k_init(const float* __restrict__ nf,
                       const float* __restrict__ w1, const float* __restrict__ b1,
                       const float* __restrict__ w2, const float* __restrict__ b2) {
    __shared__ float w1s[2 * 128];
    __shared__ float b1s[128];
    __shared__ float hidS[16 * 132];

    int tid = threadIdx.x;
    int n0 = blockIdx.x * 16;

    w1s[tid] = w1[tid];
    w1s[tid + 128] = w1[tid + 128];
    b1s[tid] = b1[tid];
    __syncthreads();

    for (int it = 0; it < 16; it++) {
        int n = n0 + it;
        float f0 = nf[n * 2 + 0];
        float f1 = nf[n * 2 + 1];
        float v = fmaf(f0, w1s[tid], fmaf(f1, w1s[128 + tid], b1s[tid]));
        hidS[it * 132 + tid] = fmaxf(v, 0.f);
    }
    __syncthreads();

    int node = tid >> 3;
    int c0 = (tid & 7) * 8;
    float acc[8];
#pragma unroll
    for (int j = 0; j < 8; j++) acc[j] = b2[c0 + j];
    for (int k = 0; k < 128; k++) {
        float hv = hidS[node * 132 + k];
#pragma unroll
        for (int j = 0; j < 8; j++) acc[j] = fmaf(hv, __ldg(w2 + k * 64 + c0 + j), acc[j]);
    }
    int n = n0 + node;
#pragma unroll
    for (int j = 0; j < 8; j++) g_h[n * 64 + c0 + j] = fmaxf(acc[j], 0.f);
}

// ---------------------------------------------------------------------------
// K_preAB: A[n] = [nf[n],h[n]] @ wA (+bias), B[n] = [nf[n],h[n]] @ wB
// Weights read directly from global (L1-cached broadcast). 256 thr, 32 nodes.
// ---------------------------------------------------------------------------
template <int OC, bool ZERO_AGG>
__global__ void k_preAB(const float* __restrict__ nf,
                        const float* __restrict__ wA,
                        const float* __restrict__ wB,
                        const float* __restrict__ bias,
                        const float* __restrict__ h,
                        float* __restrict__ outA,
                        float* __restrict__ outB,
                        float* __restrict__ agg) {
    constexpr int OC2 = 2 * OC;
    constexpr int CJ = OC2 / 32;       // 8 (OC=128) or 4 (OC=64)
    __shared__ float xS[32 * 68];

    int tid = threadIdx.x;
    int n0 = blockIdx.x * 32;

    if (ZERO_AGG) {
        for (int idx = tid; idx < 32 * 64; idx += 256) {
            int n = n0 + (idx >> 6);
            if (n < NN) agg[n * 64 + (idx & 63)] = 0.f;
        }
    }
    for (int idx = tid; idx < 32 * 64; idx += 256) {
        int i = idx >> 6, k = idx & 63;
        int n = n0 + i;
        xS[i * 68 + 2 + k] = (n < NN) ? h[n * 64 + k] : 0.f;
    }
    if (tid < 64) {
        int i = tid >> 1, f = tid & 1;
        int n = n0 + i;
        xS[i * 68 + f] = (n < NN) ? nf[n * 2 + f] : 0.f;
    }
    __syncthreads();

    int tn = (tid >> 5) * 4;
    int c0 = (tid & 31) * CJ;             // 0..OC2-CJ
    bool inA = (c0 < OC);
    int cc = inA ? c0 : (c0 - OC);
    const float* W = (inA ? wA : wB) + cc;   // row stride OC

    u64 acc[4][CJ / 2];
    {
        u64 binit[CJ / 2];
#pragma unroll
        for (int j = 0; j < CJ / 2; j++) {
            float b0 = (inA && bias) ? __ldg(bias + cc + 2 * j) : 0.f;
            float b1 = (inA && bias) ? __ldg(bias + cc + 2 * j + 1) : 0.f;
            binit[j] = pack2(b0, b1);
        }
#pragma unroll
        for (int i = 0; i < 4; i++)
#pragma unroll
            for (int j = 0; j < CJ / 2; j++) acc[i][j] = binit[j];
    }

#pragma unroll 2
    for (int k = 0; k < 66; k++) {
        const float* wr = W + k * OC;
        ulonglong2 wa = *(const ulonglong2*)wr;
        ulonglong2 wb;
        if (CJ == 8) wb = *(const ulonglong2*)(wr + 4);
#pragma unroll
        for (int i = 0; i < 4; i++) {
            u64 hh = packbc(xS[(tn + i) * 68 + k]);
            fma2(acc[i][0], hh, wa.x);
            fma2(acc[i][1], hh, wa.y);
            if (CJ == 8) {
                fma2(acc[i][2], hh, wb.x);
                fma2(acc[i][3], hh, wb.y);
            }
        }
    }

    float* OUT = (inA ? outA : outB) + cc;
#pragma unroll
    for (int i = 0; i < 4; i++) {
        int n = n0 + tn + i;
        if (n >= NN) continue;
        float vals[CJ];
#pragma unroll
        for (int j = 0; j < CJ / 2; j++) {
            float2 p = unpack2(acc[i][j]);
            vals[2 * j] = p.x; vals[2 * j + 1] = p.y;
        }
        float* o = OUT + n * OC;
#pragma unroll
        for (int j = 0; j < CJ; j += 4)
            *(float4*)(o + j) = make_float4(vals[j], vals[j + 1], vals[j + 2], vals[j + 3]);
    }
}

// ---------------------------------------------------------------------------
// K_edge (hot): hid = relu(A[dst]+B[src]+d*w132) (128); eh = relu(hid@W2+b2)
// agg[dst] += eh via red.global.add.v4. 128 edges/blk, 256 thr, 8 edges/thr.
// Stage B processes k in pairs with LDS.64 hid reads (15% fewer issue slots).
// ---------------------------------------------------------------------------
__global__ __launch_bounds__(256, 3)
void k_edge(const float* __restrict__ A, const float* __restrict__ B,
            const float* __restrict__ dist,
            const int* __restrict__ src, const int* __restrict__ dst,
            const float* __restrict__ w2, const float* __restrict__ b2,
            const float* __restrict__ w132,
            float* __restrict__ agg) {
    extern __shared__ float sm[];
    float* hidS = sm;              // 128 rows, stride 130
    __shared__ __align__(16) float w132s[128];
    __shared__ int dstS[128];
    __shared__ int srcS[128];
    __shared__ float dS[128];

    int tid = threadIdx.x;
    int e0 = blockIdx.x * 128;

    if (tid < 128) {
        w132s[tid] = w132[tid];
        dstS[tid] = dst[e0 + tid];
        srcS[tid] = src[e0 + tid];
        dS[tid] = dist[e0 + tid];
    }
    __syncthreads();

    const float4* A4 = (const float4*)A;
    const float4* B4 = (const float4*)B;
    const float4* w4 = (const float4*)w132s;

    // stage A: build 128x128 hid tile (float2 stores; stride 130)
#pragma unroll
    for (int it = 0; it < 16; it++) {
        int idx = it * 256 + tid;
        int e = idx >> 5, q = idx & 31;
        float4 a = A4[dstS[e] * 32 + q];
        float4 b = B4[srcS[e] * 32 + q];
        float4 w = w4[q];
        float d = dS[e];
        float* hp = hidS + e * 130 + q * 4;
        *(float2*)(hp) = make_float2(fmaxf(fmaf(d, w.x, a.x + b.x), 0.f),
                                     fmaxf(fmaf(d, w.y, a.y + b.y), 0.f));
        *(float2*)(hp + 2) = make_float2(fmaxf(fmaf(d, w.z, a.z + b.z), 0.f),
                                         fmaxf(fmaf(d, w.w, a.w + b.w), 0.f));
    }
    __syncthreads();

    // stage B: (128x128) @ (128x64); 8 edges x 4 cols per thread, k in pairs
    int te = (tid >> 4) * 8;      // 16 groups x 8 edges = 128
    int c0 = (tid & 15) * 4;
    u64 acc[8][2];
    {
        u64 b01 = pack2(__ldg(b2 + c0), __ldg(b2 + c0 + 1));
        u64 b23 = pack2(__ldg(b2 + c0 + 2), __ldg(b2 + c0 + 3));
#pragma unroll
        for (int i = 0; i < 8; i++) { acc[i][0] = b01; acc[i][1] = b23; }
    }

#pragma unroll 4
    for (int k0 = 0; k0 < 128; k0 += 2) {
        ulonglong2 w0 = *(const ulonglong2*)(w2 + k0 * 64 + c0);
        ulonglong2 w1 = *(const ulonglong2*)(w2 + (k0 + 1) * 64 + c0);
#pragma unroll
        for (int i = 0; i < 8; i++) {
            float2 hp = *(const float2*)(hidS + (te + i) * 130 + k0);  // LDS.64
            u64 h0 = packbc(hp.x);
            u64 h1 = packbc(hp.y);
            fma2(acc[i][0], h0, w0.x);
            fma2(acc[i][1], h0, w0.y);
            fma2(acc[i][0], h1, w1.x);
            fma2(acc[i][1], h1, w1.y);
        }
    }

#pragma unroll
    for (int i = 0; i < 8; i++) {
        float2 p0 = unpack2(acc[i][0]);
        float2 p1 = unpack2(acc[i][1]);
        float* ag = agg + dstS[te + i] * 64 + c0;   // 16B-aligned
        red_add_v4(ag, fmaxf(p0.x, 0.f), fmaxf(p0.y, 0.f),
                       fmaxf(p1.x, 0.f), fmaxf(p1.y, 0.f));
    }
}

// ---------------------------------------------------------------------------
// K_node: h = relu(relu([h, nf, agg] (130) @ nw1 + nb1) @ nw2 + nb2), in place
// 32-node tiles (grid 313), 4 rows/thread, weights via L1-cached global reads.
// ---------------------------------------------------------------------------
__global__ __launch_bounds__(256, 3)
void k_node(const float* __restrict__ nf,
            float* __restrict__ h,
            const float* __restrict__ agg,
            const float* __restrict__ w1, const float* __restrict__ b1,
            const float* __restrict__ w2, const float* __restrict__ b2) {
    extern __shared__ float sm[];
    float* xS = sm;                  // 32 x 132
    float* hidS = sm + 32 * 132;     // 32 x 132

    int tid = threadIdx.x;
    int n0 = blockIdx.x * 32;

    for (int idx = tid; idx < 32 * 64; idx += 256) {
        int i = idx >> 6, k = idx & 63;
        int n = n0 + i;
        float hv = 0.f, av = 0.f;
        if (n < NN) { hv = h[n * 64 + k]; av = agg[n * 64 + k]; }
        xS[i * 132 + k] = hv;            // rows 0..63: h
        xS[i * 132 + 66 + k] = av;       // rows 66..129: agg
    }
    if (tid < 64) {
        int i = tid >> 1, f = tid & 1;
        int n = n0 + i;
        xS[i * 132 + 64 + f] = (n < NN) ? nf[n * 2 + f] : 0.f;  // rows 64..65
    }
    __syncthreads();

    // layer 1: 32x130 @ 130x128; thread: 4 rows x 4 cols, unroll 4
    {
        int tn = (tid >> 5) * 4;
        int c0 = (tid & 31) * 4;
        u64 acc[4][2];
        u64 b01 = pack2(__ldg(b1 + c0), __ldg(b1 + c0 + 1));
        u64 b23 = pack2(__ldg(b1 + c0 + 2), __ldg(b1 + c0 + 3));
#pragma unroll
        for (int i = 0; i < 4; i++) { acc[i][0] = b01; acc[i][1] = b23; }
#pragma unroll 2
        for (int k0 = 0; k0 < 128; k0 += 4) {
            ulonglong2 wv[4];
#pragma unroll
            for (int u = 0; u < 4; u++)
                wv[u] = *(const ulonglong2*)(w1 + (k0 + u) * 128 + c0);
#pragma unroll
            for (int u = 0; u < 4; u++) {
#pragma unroll
                for (int i = 0; i < 4; i++) {
                    u64 hh = packbc(xS[(tn + i) * 132 + k0 + u]);
                    fma2(acc[i][0], hh, wv[u].x);
                    fma2(acc[i][1], hh, wv[u].y);
                }
            }
        }
        // tail k = 128, 129
#pragma unroll
        for (int k = 128; k < 130; k++) {
            ulonglong2 w = *(const ulonglong2*)(w1 + k * 128 + c0);
#pragma unroll
            for (int i = 0; i < 4; i++) {
                u64 hh = packbc(xS[(tn + i) * 132 + k]);
                fma2(acc[i][0], hh, w.x);
                fma2(acc[i][1], hh, w.y);
            }
        }
#pragma unroll
        for (int i = 0; i < 4; i++) {
            float2 p0 = unpack2(acc[i][0]), p1 = unpack2(acc[i][1]);
            *(float4*)(hidS + (tn + i) * 132 + c0) =
                make_float4(fmaxf(p0.x, 0.f), fmaxf(p0.y, 0.f),
                            fmaxf(p1.x, 0.f), fmaxf(p1.y, 0.f));
        }
    }
    __syncthreads();

    // layer 2: 32x128 @ 128x64; thread: 4 rows x 2 cols, unroll 4
    {
        int tn = (tid >> 5) * 4;
        int c0 = (tid & 31) * 2;
        u64 acc[4];
        u64 bi = pack2(__ldg(b2 + c0), __ldg(b2 + c0 + 1));
#pragma unroll
        for (int i = 0; i < 4; i++) acc[i] = bi;
#pragma unroll 4
        for (int k0 = 0; k0 < 128; k0 += 4) {
            u64 wv[4];
#pragma unroll
            for (int u = 0; u < 4; u++)
                wv[u] = *(const u64*)(w2 + (k0 + u) * 64 + c0);
#pragma unroll
            for (int u = 0; u < 4; u++) {
#pragma unroll
                for (int i = 0; i < 4; i++) {
                    u64 hh = packbc(hidS[(tn + i) * 132 + k0 + u]);
                    fma2(acc[i], hh, wv[u]);
                }
            }
        }
#pragma unroll
        for (int i = 0; i < 4; i++) {
            int n = n0 + tn + i;
            if (n < NN) {
                float2 p = unpack2(acc[i]);
                h[n * 64 + c0 + 0] = fmaxf(p.x, 0.f);
                h[n * 64 + c0 + 1] = fmaxf(p.y, 0.f);
            }
        }
    }
}

// ---------------------------------------------------------------------------
// K_cls: m = relu(Ac[dst]+Bc[src]+d*w132c) (64); out = sigmoid(m.w2 + b2)
// ---------------------------------------------------------------------------
__global__ void k_cls(const float* __restrict__ Ac, const float* __restrict__ Bc,
                      const float* __restrict__ dist,
                      const int* __restrict__ src, const int* __restrict__ dst,
                      const float* __restrict__ w132c,
                      const float* __restrict__ w2, const float* __restrict__ b2,
                      float* __restrict__ out) {
    __shared__ float w2s[64];
    __shared__ float w1s[64];
    int tid = threadIdx.x;
    if (tid < 64) { w2s[tid] = w2[tid]; w1s[tid] = w132c[tid]; }
    __syncthreads();

    int warp = tid >> 5, lane = tid & 31;
    float b2v = b2[0];
    int ebase = blockIdx.x * 64 + warp * 8;
#pragma unroll
    for (int i = 0; i < 8; i++) {
        int e = ebase + i;
        int dn = dst[e], sn = src[e];
        float d = dist[e];
        float m1 = fmaxf(fmaf(d, w1s[lane], Ac[dn * 64 + lane] + Bc[sn * 64 + lane]), 0.f);
        float m2 = fmaxf(fmaf(d, w1s[lane + 32], Ac[dn * 64 + lane + 32] + Bc[sn * 64 + lane + 32]), 0.f);
        float p = fmaf(m1, w2s[lane], m2 * w2s[lane + 32]);
#pragma unroll
        for (int o = 16; o; o >>= 1) p += __shfl_down_sync(0xffffffffu, p, o);
        if (lane == 0) out[e] = 1.f / (1.f + expf(-(p + b2v)));
    }
}

// ---------------------------------------------------------------------------

extern "C" void kernel_launch(void* const* d_in, const int* in_sizes, int n_in,
                              void* d_out, int out_size) {
    const float* nf   = (const float*)d_in[0];
    const float* dist = (const float*)d_in[1];
    const int*   src  = (const int*)d_in[2];
    const int*   dst  = (const int*)d_in[3];
    const float* iw1 = (const float*)d_in[4];
    const float* ib1 = (const float*)d_in[5];
    const float* iw2 = (const float*)d_in[6];
    const float* ib2 = (const float*)d_in[7];
    const float* ew1 = (const float*)d_in[8];
    const float* eb1 = (const float*)d_in[9];
    const float* ew2 = (const float*)d_in[10];
    const float* eb2 = (const float*)d_in[11];
    const float* nw1 = (const float*)d_in[12];
    const float* nb1 = (const float*)d_in[13];
    const float* nw2 = (const float*)d_in[14];
    const float* nb2 = (const float*)d_in[15];
    const float* cw1 = (const float*)d_in[16];
    const float* cb1 = (const float*)d_in[17];
    const float* cw2 = (const float*)d_in[18];
    const float* cb2 = (const float*)d_in[19];
    float* out = (float*)d_out;

    float *pA, *pB, *pH, *pAgg;
    cudaGetSymbolAddress((void**)&pA, g_A);
    cudaGetSymbolAddress((void**)&pB, g_B);
    cudaGetSymbolAddress((void**)&pH, g_h);
    cudaGetSymbolAddress((void**)&pAgg, g_agg);

    const int EDGE_SMEM = 128 * 130 * 4;        // 66560
    const int NODE_SMEM = 2 * 32 * 132 * 4;     // 33792
    cudaFuncSetAttribute(k_edge, cudaFuncAttributeMaxDynamicSharedMemorySize, EDGE_SMEM);
    cudaFuncSetAttribute(k_node, cudaFuncAttributeMaxDynamicSharedMemorySize, NODE_SMEM);

    const int PRE_BLOCKS  = (NN + 31) / 32;    // 313
    const int NODE_BLOCKS = (NN + 31) / 32;    // 313
    const int EDGE_BLOCKS = NE / 128;          // 1250

    k_init<<<NN / 16, 128>>>(nf, iw1, ib1, iw2, ib2);

    for (int it = 0; it < ITERS; it++) {
        k_preAB<128, true><<<PRE_BLOCKS, 256>>>(nf, ew1, ew1 + 66 * 128,
                                                eb1, pH, pA, pB, pAgg);
        k_edge<<<EDGE_BLOCKS, 256, EDGE_SMEM>>>(pA, pB, dist, src, dst,
                                                ew2, eb2, ew1 + 132 * 128, pAgg);
        k_node<<<NODE_BLOCKS, 256, NODE_SMEM>>>(nf, pH, pAgg, nw1, nb1, nw2, nb2);
    }

    k_preAB<64, false><<<PRE_BLOCKS, 256>>>(nf, cw1, cw1 + 66 * 64,
                                            cb1, pH, pA, pB, nullptr);
    k_cls<<<NE / 64, 256>>>(pA, pB, dist, src, dst,
                            cw1 + 132 * 64, cw2, cb2, out);
}

// round 12
// speedup vs baseline: 1.0612x; 1.0141x over previous
#include <cuda_runtime.h>
#include <math.h>

#define NN 10000
#define NE 160000
#define HID 128
#define EMB 64
#define ITERS 16

typedef unsigned long long u64;

// ---------------- packed f32x2 helpers (Blackwell FFMA2) --------------------
__device__ __forceinline__ u64 pack2(float x, float y) {
    u64 r; asm("mov.b64 %0, {%1, %2};" : "=l"(r) : "f"(x), "f"(y)); return r;
}
__device__ __forceinline__ u64 packbc(float x) {
    u64 r; asm("mov.b64 %0, {%1, %1};" : "=l"(r) : "f"(x)); return r;
}
__device__ __forceinline__ void fma2(u64 &d, u64 a, u64 b) {
    asm("fma.rn.f32x2 %0, %1, %2, %0;" : "+l"(d) : "l"(a), "l"(b));
}
__device__ __forceinline__ float2 unpack2(u64 v) {
    float2 o; asm("mov.b64 {%0, %1}, %2;" : "=f"(o.x), "=f"(o.y) : "l"(v)); return o;
}
__device__ __forceinline__ void red_add_v4(float* p, float a, float b, float c, float d) {
    asm volatile("red.global.add.v4.f32 [%0], {%1, %2, %3, %4};"
                 :: "l"(p), "f"(a), "f"(b), "f"(c), "f"(d) : "memory");
}

// ---------------- scratch (device globals; no allocation) -------------------
__device__ __align__(16) float g_h[NN * EMB];
__device__ __align__(16) float g_A[NN * HID];
__device__ __align__(16) float g_B[NN * HID];
__device__ __align__(16) float g_agg[NN * EMB];
__device__ int g_off[NN];
__device__ int g_srcP[NE];
__device__ int g_dstP[NE];
__device__ __align__(8) float g_distP[NE];

// ---------------------------------------------------------------------------
// K_csr_build: one block; smem histogram of dst + exclusive scan -> g_off.
// ---------------------------------------------------------------------------
__global__ void k_csr_build(const int* __restrict__ dst, int* __restrict__ off) {
    __shared__ int scnt[NN];
    __shared__ int ps[1024];
    int t = threadIdx.x;

    for (int i = t; i < NN; i += 1024) scnt[i] = 0;
    __syncthreads();

    for (int e = t; e < NE; e += 1024) atomicAdd(&scnt[dst[e]], 1);
    __syncthreads();

    int base = t * 10;
    int s = 0;
#pragma unroll
    for (int j = 0; j < 10; j++) { int i = base + j; if (i < NN) s += scnt[i]; }
    ps[t] = s;
    __syncthreads();
    for (int o = 1; o < 1024; o <<= 1) {
        int v = (t >= o) ? ps[t - o] : 0;
        __syncthreads();
        ps[t] += v;
        __syncthreads();
    }
    int run = (t == 0) ? 0 : ps[t - 1];
#pragma unroll
    for (int j = 0; j < 10; j++) {
        int i = base + j;
        if (i < NN) { off[i] = run; run += scnt[i]; }
    }
}

// ---------------------------------------------------------------------------
// K_fill: scatter edges into dst-sorted order.
// ---------------------------------------------------------------------------
__global__ void k_fill(const int* __restrict__ src, const int* __restrict__ dst,
                       const float* __restrict__ dist, int* __restrict__ off,
                       int* __restrict__ srcP, int* __restrict__ dstP,
                       float* __restrict__ distP) {
    int e = blockIdx.x * 256 + threadIdx.x;
    if (e < NE) {
        int d = dst[e];
        int p = atomicAdd(&off[d], 1);
        srcP[p] = src[e];
        dstP[p] = d;
        distP[p] = dist[e];
    }
}

// ---------------------------------------------------------------------------
// K_init: h = relu(relu(nf @ iw1 + ib1) @ iw2 + ib2). 128 thr, 16 nodes/blk.
// ---------------------------------------------------------------------------
__global__ void k_init(const float* __restrict__ nf,
                       const float* __restrict__ w1, const float* __restrict__ b1,
                       const float* __restrict__ w2, const float* __restrict__ b2) {
    __shared__ float w1s[2 * 128];
    __shared__ float b1s[128];
    __shared__ float hidS[16 * 132];

    int tid = threadIdx.x;
    int n0 = blockIdx.x * 16;

    w1s[tid] = w1[tid];
    w1s[tid + 128] = w1[tid + 128];
    b1s[tid] = b1[tid];
    __syncthreads();

    for (int it = 0; it < 16; it++) {
        int n = n0 + it;
        float f0 = nf[n * 2 + 0];
        float f1 = nf[n * 2 + 1];
        float v = fmaf(f0, w1s[tid], fmaf(f1, w1s[128 + tid], b1s[tid]));
        hidS[it * 132 + tid] = fmaxf(v, 0.f);
    }
    __syncthreads();

    int node = tid >> 3;
    int c0 = (tid & 7) * 8;
    float acc[8];
#pragma unroll
    for (int j = 0; j < 8; j++) acc[j] = b2[c0 + j];
    for (int k = 0; k < 128; k++) {
        float hv = hidS[node * 132 + k];
#pragma unroll
        for (int j = 0; j < 8; j++) acc[j] = fmaf(hv, __ldg(w2 + k * 64 + c0 + j), acc[j]);
    }
    int n = n0 + node;
#pragma unroll
    for (int j = 0; j < 8; j++) g_h[n * 64 + c0 + j] = fmaxf(acc[j], 0.f);
}

// ---------------------------------------------------------------------------
// K_preAB: A[n] = [nf[n],h[n]] @ wA (+bias), B[n] = [nf[n],h[n]] @ wB
// Weights read directly from global (L1-cached broadcast). 256 thr, 32 nodes.
// ---------------------------------------------------------------------------
template <int OC, bool ZERO_AGG>
__global__ void k_preAB(const float* __restrict__ nf,
                        const float* __restrict__ wA,
                        const float* __restrict__ wB,
                        const float* __restrict__ bias,
                        const float* __restrict__ h,
                        float* __restrict__ outA,
                        float* __restrict__ outB,
                        float* __restrict__ agg) {
    constexpr int OC2 = 2 * OC;
    constexpr int CJ = OC2 / 32;       // 8 (OC=128) or 4 (OC=64)
    __shared__ float xS[32 * 68];

    int tid = threadIdx.x;
    int n0 = blockIdx.x * 32;

    if (ZERO_AGG) {
        for (int idx = tid; idx < 32 * 64; idx += 256) {
            int n = n0 + (idx >> 6);
            if (n < NN) agg[n * 64 + (idx & 63)] = 0.f;
        }
    }
    for (int idx = tid; idx < 32 * 64; idx += 256) {
        int i = idx >> 6, k = idx & 63;
        int n = n0 + i;
        xS[i * 68 + 2 + k] = (n < NN) ? h[n * 64 + k] : 0.f;
    }
    if (tid < 64) {
        int i = tid >> 1, f = tid & 1;
        int n = n0 + i;
        xS[i * 68 + f] = (n < NN) ? nf[n * 2 + f] : 0.f;
    }
    __syncthreads();

    int tn = (tid >> 5) * 4;
    int c0 = (tid & 31) * CJ;             // 0..OC2-CJ
    bool inA = (c0 < OC);
    int cc = inA ? c0 : (c0 - OC);
    const float* W = (inA ? wA : wB) + cc;   // row stride OC

    u64 acc[4][CJ / 2];
    {
        u64 binit[CJ / 2];
#pragma unroll
        for (int j = 0; j < CJ / 2; j++) {
            float b0 = (inA && bias) ? __ldg(bias + cc + 2 * j) : 0.f;
            float b1 = (inA && bias) ? __ldg(bias + cc + 2 * j + 1) : 0.f;
            binit[j] = pack2(b0, b1);
        }
#pragma unroll
        for (int i = 0; i < 4; i++)
#pragma unroll
            for (int j = 0; j < CJ / 2; j++) acc[i][j] = binit[j];
    }

#pragma unroll 2
    for (int k = 0; k < 66; k++) {
        const float* wr = W + k * OC;
        ulonglong2 wa = *(const ulonglong2*)wr;
        ulonglong2 wb;
        if (CJ == 8) wb = *(const ulonglong2*)(wr + 4);
#pragma unroll
        for (int i = 0; i < 4; i++) {
            u64 hh = packbc(xS[(tn + i) * 68 + k]);
            fma2(acc[i][0], hh, wa.x);
            fma2(acc[i][1], hh, wa.y);
            if (CJ == 8) {
                fma2(acc[i][2], hh, wb.x);
                fma2(acc[i][3], hh, wb.y);
            }
        }
    }

    float* OUT = (inA ? outA : outB) + cc;
#pragma unroll
    for (int i = 0; i < 4; i++) {
        int n = n0 + tn + i;
        if (n >= NN) continue;
        float vals[CJ];
#pragma unroll
        for (int j = 0; j < CJ / 2; j++) {
            float2 p = unpack2(acc[i][j]);
            vals[2 * j] = p.x; vals[2 * j + 1] = p.y;
        }
        float* o = OUT + n * OC;
#pragma unroll
        for (int j = 0; j < CJ; j += 4)
            *(float4*)(o + j) = make_float4(vals[j], vals[j + 1], vals[j + 2], vals[j + 3]);
    }
}

// ---------------------------------------------------------------------------
// K_edge (hot): consumes dst-SORTED edge stream. hid = relu(A[dst]+B[src]+d*w)
// then eh = relu(hid@W2+b2); same-dst runs merged in registers before red.v4.
// 128 edges/blk, 256 thr, 8 edges/thr.
// ---------------------------------------------------------------------------
__global__ __launch_bounds__(256, 3)
void k_edge(const float* __restrict__ A, const float* __restrict__ B,
            const float* __restrict__ distP,
            const int* __restrict__ srcP, const int* __restrict__ dstP,
            const float* __restrict__ w2, const float* __restrict__ b2,
            const float* __restrict__ w132,
            float* __restrict__ agg) {
    extern __shared__ float sm[];
    float* hidS = sm;              // 128 rows, stride 130
    __shared__ __align__(16) float w132s[128];
    __shared__ int dstS[128];
    __shared__ int srcS[128];
    __shared__ float dS[128];

    int tid = threadIdx.x;
    int e0 = blockIdx.x * 128;

    if (tid < 128) {
        w132s[tid] = w132[tid];
        dstS[tid] = dstP[e0 + tid];
        srcS[tid] = srcP[e0 + tid];
        dS[tid] = distP[e0 + tid];
    }
    __syncthreads();

    const float4* A4 = (const float4*)A;
    const float4* B4 = (const float4*)B;
    const float4* w4 = (const float4*)w132s;

    // stage A: build 128x128 hid tile (float2 stores; stride 130)
#pragma unroll
    for (int it = 0; it < 16; it++) {
        int idx = it * 256 + tid;
        int e = idx >> 5, q = idx & 31;
        float4 a = A4[dstS[e] * 32 + q];
        float4 b = B4[srcS[e] * 32 + q];
        float4 w = w4[q];
        float d = dS[e];
        float* hp = hidS + e * 130 + q * 4;
        *(float2*)(hp) = make_float2(fmaxf(fmaf(d, w.x, a.x + b.x), 0.f),
                                     fmaxf(fmaf(d, w.y, a.y + b.y), 0.f));
        *(float2*)(hp + 2) = make_float2(fmaxf(fmaf(d, w.z, a.z + b.z), 0.f),
                                         fmaxf(fmaf(d, w.w, a.w + b.w), 0.f));
    }
    __syncthreads();

    // stage B: (128x128) @ (128x64); 8 edges x 4 cols per thread
    int te = (tid >> 4) * 8;      // 16 groups x 8 edges = 128
    int c0 = (tid & 15) * 4;
    u64 acc[8][2];
    {
        u64 b01 = pack2(__ldg(b2 + c0), __ldg(b2 + c0 + 1));
        u64 b23 = pack2(__ldg(b2 + c0 + 2), __ldg(b2 + c0 + 3));
#pragma unroll
        for (int i = 0; i < 8; i++) { acc[i][0] = b01; acc[i][1] = b23; }
    }

#pragma unroll 4
    for (int k = 0; k < 128; k++) {
        ulonglong2 w = *(const ulonglong2*)(w2 + k * 64 + c0);
#pragma unroll
        for (int i = 0; i < 8; i++) {
            u64 hh = packbc(hidS[(te + i) * 130 + k]);
            fma2(acc[i][0], hh, w.x);
            fma2(acc[i][1], hh, w.y);
        }
    }

    // epilogue: relu, merge consecutive same-dst edges, one red.v4 per run
    {
        int cur = dstS[te];
        float2 p0 = unpack2(acc[0][0]), p1 = unpack2(acc[0][1]);
        float s0 = fmaxf(p0.x, 0.f), s1 = fmaxf(p0.y, 0.f);
        float s2 = fmaxf(p1.x, 0.f), s3 = fmaxf(p1.y, 0.f);
#pragma unroll
        for (int i = 1; i < 8; i++) {
            float2 q0 = unpack2(acc[i][0]), q1 = unpack2(acc[i][1]);
            float v0 = fmaxf(q0.x, 0.f), v1 = fmaxf(q0.y, 0.f);
            float v2 = fmaxf(q1.x, 0.f), v3 = fmaxf(q1.y, 0.f);
            int dn = dstS[te + i];
            if (dn == cur) {
                s0 += v0; s1 += v1; s2 += v2; s3 += v3;
            } else {
                red_add_v4(agg + cur * 64 + c0, s0, s1, s2, s3);
                cur = dn; s0 = v0; s1 = v1; s2 = v2; s3 = v3;
            }
        }
        red_add_v4(agg + cur * 64 + c0, s0, s1, s2, s3);
    }
}

// ---------------------------------------------------------------------------
// K_node: h = relu(relu([h, nf, agg] (130) @ nw1 + nb1) @ nw2 + nb2), in place
// 32-node tiles (grid 313), 4 rows/thread, weights via L1-cached global reads.
// ---------------------------------------------------------------------------
__global__ __launch_bounds__(256, 3)
void k_node(const float* __restrict__ nf,
            float* __restrict__ h,
            const float* __restrict__ agg,
            const float* __restrict__ w1, const float* __restrict__ b1,
            const float* __restrict__ w2, const float* __restrict__ b2) {
    extern __shared__ float sm[];
    float* xS = sm;                  // 32 x 132
    float* hidS = sm + 32 * 132;     // 32 x 132

    int tid = threadIdx.x;
    int n0 = blockIdx.x * 32;

    for (int idx = tid; idx < 32 * 64; idx += 256) {
        int i = idx >> 6, k = idx & 63;
        int n = n0 + i;
        float hv = 0.f, av = 0.f;
        if (n < NN) { hv = h[n * 64 + k]; av = agg[n * 64 + k]; }
        xS[i * 132 + k] = hv;            // rows 0..63: h
        xS[i * 132 + 66 + k] = av;       // rows 66..129: agg
    }
    if (tid < 64) {
        int i = tid >> 1, f = tid & 1;
        int n = n0 + i;
        xS[i * 132 + 64 + f] = (n < NN) ? nf[n * 2 + f] : 0.f;  // rows 64..65
    }
    __syncthreads();

    // layer 1: 32x130 @ 130x128; thread: 4 rows x 4 cols, unroll 4
    {
        int tn = (tid >> 5) * 4;
        int c0 = (tid & 31) * 4;
        u64 acc[4][2];
        u64 b01 = pack2(__ldg(b1 + c0), __ldg(b1 + c0 + 1));
        u64 b23 = pack2(__ldg(b1 + c0 + 2), __ldg(b1 + c0 + 3));
#pragma unroll
        for (int i = 0; i < 4; i++) { acc[i][0] = b01; acc[i][1] = b23; }
#pragma unroll 2
        for (int k0 = 0; k0 < 128; k0 += 4) {
            ulonglong2 wv[4];
#pragma unroll
            for (int u = 0; u < 4; u++)
                wv[u] = *(const ulonglong2*)(w1 + (k0 + u) * 128 + c0);
#pragma unroll
            for (int u = 0; u < 4; u++) {
#pragma unroll
                for (int i = 0; i < 4; i++) {
                    u64 hh = packbc(xS[(tn + i) * 132 + k0 + u]);
                    fma2(acc[i][0], hh, wv[u].x);
                    fma2(acc[i][1], hh, wv[u].y);
                }
            }
        }
        // tail k = 128, 129
#pragma unroll
        for (int k = 128; k < 130; k++) {
            ulonglong2 w = *(const ulonglong2*)(w1 + k * 128 + c0);
#pragma unroll
            for (int i = 0; i < 4; i++) {
                u64 hh = packbc(xS[(tn + i) * 132 + k]);
                fma2(acc[i][0], hh, w.x);
                fma2(acc[i][1], hh, w.y);
            }
        }
#pragma unroll
        for (int i = 0; i < 4; i++) {
            float2 p0 = unpack2(acc[i][0]), p1 = unpack2(acc[i][1]);
            *(float4*)(hidS + (tn + i) * 132 + c0) =
                make_float4(fmaxf(p0.x, 0.f), fmaxf(p0.y, 0.f),
                            fmaxf(p1.x, 0.f), fmaxf(p1.y, 0.f));
        }
    }
    __syncthreads();

    // layer 2: 32x128 @ 128x64; thread: 4 rows x 2 cols, unroll 4
    {
        int tn = (tid >> 5) * 4;
        int c0 = (tid & 31) * 2;
        u64 acc[4];
        u64 bi = pack2(__ldg(b2 + c0), __ldg(b2 + c0 + 1));
#pragma unroll
        for (int i = 0; i < 4; i++) acc[i] = bi;
#pragma unroll 4
        for (int k0 = 0; k0 < 128; k0 += 4) {
            u64 wv[4];
#pragma unroll
            for (int u = 0; u < 4; u++)
                wv[u] = *(const u64*)(w2 + (k0 + u) * 64 + c0);
#pragma unroll
            for (int u = 0; u < 4; u++) {
#pragma unroll
                for (int i = 0; i < 4; i++) {
                    u64 hh = packbc(hidS[(tn + i) * 132 + k0 + u]);
                    fma2(acc[i], hh, wv[u]);
                }
            }
        }
#pragma unroll
        for (int i = 0; i < 4; i++) {
            int n = n0 + tn + i;
            if (n < NN) {
                float2 p = unpack2(acc[i]);
                h[n * 64 + c0 + 0] = fmaxf(p.x, 0.f);
                h[n * 64 + c0 + 1] = fmaxf(p.y, 0.f);
            }
        }
    }
}

// ---------------------------------------------------------------------------
// K_cls: m = relu(Ac[dst]+Bc[src]+d*w132c) (64); out = sigmoid(m.w2 + b2)
// Uses ORIGINAL (unsorted) edge arrays — output order must match reference.
// ---------------------------------------------------------------------------
__global__ void k_cls(const float* __restrict__ Ac, const float* __restrict__ Bc,
                      const float* __restrict__ dist,
                      const int* __restrict__ src, const int* __restrict__ dst,
                      const float* __restrict__ w132c,
                      const float* __restrict__ w2, const float* __restrict__ b2,
                      float* __restrict__ out) {
    __shared__ float w2s[64];
    __shared__ float w1s[64];
    int tid = threadIdx.x;
    if (tid < 64) { w2s[tid] = w2[tid]; w1s[tid] = w132c[tid]; }
    __syncthreads();

    int warp = tid >> 5, lane = tid & 31;
    float b2v = b2[0];
    int ebase = blockIdx.x * 64 + warp * 8;
#pragma unroll
    for (int i = 0; i < 8; i++) {
        int e = ebase + i;
        int dn = dst[e], sn = src[e];
        float d = dist[e];
        float m1 = fmaxf(fmaf(d, w1s[lane], Ac[dn * 64 + lane] + Bc[sn * 64 + lane]), 0.f);
        float m2 = fmaxf(fmaf(d, w1s[lane + 32], Ac[dn * 64 + lane + 32] + Bc[sn * 64 + lane + 32]), 0.f);
        float p = fmaf(m1, w2s[lane], m2 * w2s[lane + 32]);
#pragma unroll
        for (int o = 16; o; o >>= 1) p += __shfl_down_sync(0xffffffffu, p, o);
        if (lane == 0) out[e] = 1.f / (1.f + expf(-(p + b2v)));
    }
}

// ---------------------------------------------------------------------------

extern "C" void kernel_launch(void* const* d_in, const int* in_sizes, int n_in,
                              void* d_out, int out_size) {
    const float* nf   = (const float*)d_in[0];
    const float* dist = (const float*)d_in[1];
    const int*   src  = (const int*)d_in[2];
    const int*   dst  = (const int*)d_in[3];
    const float* iw1 = (const float*)d_in[4];
    const float* ib1 = (const float*)d_in[5];
    const float* iw2 = (const float*)d_in[6];
    const float* ib2 = (const float*)d_in[7];
    const float* ew1 = (const float*)d_in[8];
    const float* eb1 = (const float*)d_in[9];
    const float* ew2 = (const float*)d_in[10];
    const float* eb2 = (const float*)d_in[11];
    const float* nw1 = (const float*)d_in[12];
    const float* nb1 = (const float*)d_in[13];
    const float* nw2 = (const float*)d_in[14];
    const float* nb2 = (const float*)d_in[15];
    const float* cw1 = (const float*)d_in[16];
    const float* cb1 = (const float*)d_in[17];
    const float* cw2 = (const float*)d_in[18];
    const float* cb2 = (const float*)d_in[19];
    float* out = (float*)d_out;

    float *pA, *pB, *pH, *pAgg, *pDistP;
    int *pOff, *pSrcP, *pDstP;
    cudaGetSymbolAddress((void**)&pA, g_A);
    cudaGetSymbolAddress((void**)&pB, g_B);
    cudaGetSymbolAddress((void**)&pH, g_h);
    cudaGetSymbolAddress((void**)&pAgg, g_agg);
    cudaGetSymbolAddress((void**)&pOff, g_off);
    cudaGetSymbolAddress((void**)&pSrcP, g_srcP);
    cudaGetSymbolAddress((void**)&pDstP, g_dstP);
    cudaGetSymbolAddress((void**)&pDistP, g_distP);

    const int EDGE_SMEM = 128 * 130 * 4;        // 66560
    const int NODE_SMEM = 2 * 32 * 132 * 4;     // 33792
    cudaFuncSetAttribute(k_edge, cudaFuncAttributeMaxDynamicSharedMemorySize, EDGE_SMEM);
    cudaFuncSetAttribute(k_node, cudaFuncAttributeMaxDynamicSharedMemorySize, NODE_SMEM);

    const int PRE_BLOCKS  = (NN + 31) / 32;    // 313
    const int NODE_BLOCKS = (NN + 31) / 32;    // 313
    const int EDGE_BLOCKS = NE / 128;          // 1250

    // 1..3: init + one-time dst-sort of the edge stream
    k_init<<<NN / 16, 128>>>(nf, iw1, ib1, iw2, ib2);
    k_csr_build<<<1, 1024>>>(dst, pOff);
    k_fill<<<(NE + 255) / 256, 256>>>(src, dst, dist, pOff, pSrcP, pDstP, pDistP);

    for (int it = 0; it < ITERS; it++) {
        k_preAB<128, true><<<PRE_BLOCKS, 256>>>(nf, ew1, ew1 + 66 * 128,
                                                eb1, pH, pA, pB, pAgg);   // launch #4: profiled
        k_edge<<<EDGE_BLOCKS, 256, EDGE_SMEM>>>(pA, pB, pDistP, pSrcP, pDstP,
                                                ew2, eb2, ew1 + 132 * 128, pAgg);
        k_node<<<NODE_BLOCKS, 256, NODE_SMEM>>>(nf, pH, pAgg, nw1, nb1, nw2, nb2);
    }

    k_preAB<64, false><<<PRE_BLOCKS, 256>>>(nf, cw1, cw1 + 66 * 64,
                                            cb1, pH, pA, pB, nullptr);
    k_cls<<<NE / 64, 256>>>(pA, pB, dist, src, dst,
                            cw1 + 132 * 64, cw2, cb2, out);
}